// round 1
// baseline (speedup 1.0000x reference)
#include <cuda_runtime.h>

// Problem shapes
#define B_ 128
#define S_ 37
#define T_ 2048
#define D_ 256
#define ST_ 8
#define C_ 2
#define MERGED_ 264
#define NF (2*S_)          // 74 features (x ++ mask)
#define TC 128             // time chunk per CTA
#define NCHUNK (T_/TC)     // 16

// Per-chunk partial reductions (written without atomics -> deterministic)
__device__ float g_px[(size_t)NCHUNK * B_ * NF];  // sum_t valid * x_time[f]
__device__ float g_pm[NCHUNK * B_];               // sum_t valid
__device__ float g_pt[NCHUNK * B_];               // sum_t valid * time

__device__ __forceinline__ float wred(float v) {
#pragma unroll
    for (int o = 16; o > 0; o >>= 1) v += __shfl_xor_sync(0xffffffffu, v, o);
    return v;
}

// ---------------------------------------------------------------------------
// Stage 1: DRAM-bound pass. Stage a [37 sensors x 128 t] tile of x and mask
// in smem (coalesced float4/int4), compute per-timestep valid flag across all
// 74 features, then warp-per-feature masked sums.
// ---------------------------------------------------------------------------
__global__ __launch_bounds__(256) void stage1(const float* __restrict__ x,
                                              const int*   __restrict__ smk,
                                              const float* __restrict__ tm) {
    __shared__ float xs[S_ * TC];
    __shared__ float ms[S_ * TC];
    __shared__ float valid[TC];
    __shared__ float red[8][2];

    const int chunk = blockIdx.x;
    const int b     = blockIdx.y;
    const int t0    = chunk * TC;

    const float* xb = x   + (size_t)b * S_ * T_ + t0;
    const int*   mb = smk + (size_t)b * S_ * T_ + t0;

    // Load tile: 37 rows of 128 floats + 128 ints, vectorized 16B.
    for (int idx = threadIdx.x; idx < S_ * (TC / 4); idx += 256) {
        int s = idx / (TC / 4);
        int j = (idx % (TC / 4)) * 4;
        float4 v = *(const float4*)(xb + (size_t)s * T_ + j);
        *(float4*)(xs + s * TC + j) = v;
        int4 m = *(const int4*)(mb + (size_t)s * T_ + j);
        *(float4*)(ms + s * TC + j) =
            make_float4((float)m.x, (float)m.y, (float)m.z, (float)m.w);
    }
    __syncthreads();

    // Per-timestep valid flag (any of the 74 features nonzero).
    float vf = 0.f, tv = 0.f;
    if (threadIdx.x < TC) {
        const int t = threadIdx.x;
        int nz = 0;
#pragma unroll
        for (int s = 0; s < S_; s++) {
            nz |= (xs[s * TC + t] != 0.f);
            nz |= (ms[s * TC + t] != 0.f);
        }
        vf = nz ? 1.f : 0.f;
        valid[t] = vf;
        tv = vf * tm[(size_t)b * T_ + t0 + t];
    }

    // Block-reduce mask count and masked time.
    const int w = threadIdx.x >> 5, lane = threadIdx.x & 31;
    float rv = wred(vf), rt = wred(tv);
    if (lane == 0) { red[w][0] = rv; red[w][1] = rt; }
    __syncthreads();   // also makes valid[] visible to all warps
    if (threadIdx.x == 0) {
        float a = 0.f, c = 0.f;
#pragma unroll
        for (int i = 0; i < 8; i++) { a += red[i][0]; c += red[i][1]; }
        g_pm[chunk * B_ + b] = a;
        g_pt[chunk * B_ + b] = c;
    }

    // Masked per-feature sums: warp w handles features w, w+8, ...
    for (int f = w; f < NF; f += 8) {
        const float* src = (f < S_) ? (xs + f * TC) : (ms + (f - S_) * TC);
        float p = 0.f;
#pragma unroll
        for (int j = lane; j < TC; j += 32) p += valid[j] * src[j];
        p = wred(p);
        if (lane == 0) g_px[((size_t)chunk * B_ + b) * NF + f] = p;
    }
}

// ---------------------------------------------------------------------------
// Stage 2: per-batch tiny MLP. One CTA per batch row, 256 threads.
// ---------------------------------------------------------------------------
__global__ __launch_bounds__(256) void stage2(
    const float* __restrict__ stat,
    const float* __restrict__ Ws,  const float* __restrict__ bs,
    const float* __restrict__ Wt,  const float* __restrict__ bt,
    const float* __restrict__ Wst, const float* __restrict__ bst,
    const float* __restrict__ Wm,  const float* __restrict__ bm,
    const float* __restrict__ Wc,  const float* __restrict__ bc,
    float* __restrict__ out) {
    __shared__ float xsum[NF];
    __shared__ float comb[MERGED_];
    __shared__ float comb2[MERGED_];
    __shared__ float sden[2];   // [0]=denom, [1]=tsum/denom

    const int b = blockIdx.x;
    const int tid = threadIdx.x;

    // Reduce per-chunk partials.
    if (tid < NF) {
        float a = 0.f;
#pragma unroll
        for (int c = 0; c < NCHUNK; c++) a += g_px[((size_t)c * B_ + b) * NF + tid];
        xsum[tid] = a;
    }
    if (tid == NF) {
        float a = 0.f, t = 0.f;
#pragma unroll
        for (int c = 0; c < NCHUNK; c++) { a += g_pm[c * B_ + b]; t += g_pt[c * B_ + b]; }
        float den = fmaxf(a, 1e-9f);
        sden[0] = den;
        sden[1] = t / den;
    }
    __syncthreads();

    const float den = sden[0], tsc = sden[1];

    // pooled[d] + time/bias terms: each thread owns one of 256 dims.
    {
        float p = 0.f;
#pragma unroll 2
        for (int f = 0; f < NF; f++) p += xsum[f] * Ws[f * D_ + tid];
        comb[tid] = p / den + bs[tid] + bt[tid] + tsc * Wt[tid];
    }
    // static embedding (8 dims).
    if (tid < ST_) {
        float p = bst[tid];
#pragma unroll
        for (int i = 0; i < ST_; i++) p += stat[b * ST_ + i] * Wst[i * ST_ + tid];
        comb[D_ + tid] = p;
    }
    __syncthreads();

    // merge: relu(comb @ Wm + bm), 264 outputs over 256 threads.
    {
        float p = bm[tid];
        for (int i = 0; i < MERGED_; i++) p += comb[i] * Wm[i * MERGED_ + tid];
        comb2[tid] = fmaxf(p, 0.f);
    }
    if (tid < MERGED_ - D_) {
        const int j = D_ + tid;
        float p = bm[j];
        for (int i = 0; i < MERGED_; i++) p += comb[i] * Wm[i * MERGED_ + j];
        comb2[j] = fmaxf(p, 0.f);
    }
    __syncthreads();

    // classifier: warp 0 -> class 0, warp 1 -> class 1.
    const int w = tid >> 5, lane = tid & 31;
    if (w < C_) {
        float p = 0.f;
        for (int i = lane; i < MERGED_; i += 32) p += comb2[i] * Wc[i * C_ + w];
        p = wred(p);
        if (lane == 0) out[b * C_ + w] = p + bc[w];
    }
}

extern "C" void kernel_launch(void* const* d_in, const int* in_sizes, int n_in,
                              void* d_out, int out_size) {
    const float* x   = (const float*)d_in[0];
    const float* st  = (const float*)d_in[1];
    const float* tm  = (const float*)d_in[2];
    const int*   smk = (const int*)  d_in[3];
    const float* Ws  = (const float*)d_in[4];
    const float* bs  = (const float*)d_in[5];
    const float* Wt  = (const float*)d_in[6];
    const float* bt  = (const float*)d_in[7];
    const float* Wst = (const float*)d_in[8];
    const float* bst = (const float*)d_in[9];
    const float* Wm  = (const float*)d_in[10];
    const float* bm  = (const float*)d_in[11];
    const float* Wc  = (const float*)d_in[12];
    const float* bc  = (const float*)d_in[13];

    stage1<<<dim3(NCHUNK, B_), 256>>>(x, smk, tm);
    stage2<<<B_, 256>>>(st, Ws, bs, Wt, bt, Wst, bst, Wm, bm, Wc, bc,
                        (float*)d_out);
}

// round 3
// speedup vs baseline: 1.3706x; 1.3706x over previous
#include <cuda_runtime.h>

// Problem shapes
#define B_ 128
#define S_ 37
#define T_ 2048
#define D_ 256
#define ST_ 8
#define C_ 2
#define MERGED_ 264
#define NF (2*S_)          // 74 features (x ++ mask)
#define TC 128             // time chunk per CTA
#define NCHUNK (T_/TC)     // 16

// Per-chunk partial reductions (written without atomics -> deterministic)
__device__ float g_px[(size_t)NCHUNK * B_ * NF];  // sum_t valid * x_time[f]
__device__ float g_pm[NCHUNK * B_];               // sum_t valid
__device__ float g_pt[NCHUNK * B_];               // sum_t valid * time

__device__ __forceinline__ float wred(float v) {
#pragma unroll
    for (int o = 16; o > 0; o >>= 1) v += __shfl_xor_sync(0xffffffffu, v, o);
    return v;
}

// ---------------------------------------------------------------------------
// Stage 1: DRAM/L2-bound pass. Stage a [37 sensors x 128 t] tile of x and
// mask in smem (coalesced float4/int4), compute per-timestep valid flag
// across all 74 features, then warp-per-feature masked sums.
// ---------------------------------------------------------------------------
__global__ __launch_bounds__(256) void stage1(const float* __restrict__ x,
                                              const int*   __restrict__ smk,
                                              const float* __restrict__ tm) {
    __shared__ float xs[S_ * TC];
    __shared__ float ms[S_ * TC];
    __shared__ float valid[TC];
    __shared__ float red[8][2];

    const int chunk = blockIdx.x;
    const int b     = blockIdx.y;
    const int t0    = chunk * TC;

    const float* xb = x   + (size_t)b * S_ * T_ + t0;
    const int*   mb = smk + (size_t)b * S_ * T_ + t0;

    for (int idx = threadIdx.x; idx < S_ * (TC / 4); idx += 256) {
        int s = idx / (TC / 4);
        int j = (idx % (TC / 4)) * 4;
        float4 v = *(const float4*)(xb + (size_t)s * T_ + j);
        *(float4*)(xs + s * TC + j) = v;
        int4 m = *(const int4*)(mb + (size_t)s * T_ + j);
        *(float4*)(ms + s * TC + j) =
            make_float4((float)m.x, (float)m.y, (float)m.z, (float)m.w);
    }
    __syncthreads();

    float vf = 0.f, tv = 0.f;
    if (threadIdx.x < TC) {
        const int t = threadIdx.x;
        int nz = 0;
#pragma unroll
        for (int s = 0; s < S_; s++) {
            nz |= (xs[s * TC + t] != 0.f);
            nz |= (ms[s * TC + t] != 0.f);
        }
        vf = nz ? 1.f : 0.f;
        valid[t] = vf;
        tv = vf * tm[(size_t)b * T_ + t0 + t];
    }

    const int w = threadIdx.x >> 5, lane = threadIdx.x & 31;
    float rv = wred(vf), rt = wred(tv);
    if (lane == 0) { red[w][0] = rv; red[w][1] = rt; }
    __syncthreads();   // also makes valid[] visible to all warps
    if (threadIdx.x == 0) {
        float a = 0.f, c = 0.f;
#pragma unroll
        for (int i = 0; i < 8; i++) { a += red[i][0]; c += red[i][1]; }
        g_pm[chunk * B_ + b] = a;
        g_pt[chunk * B_ + b] = c;
    }

    for (int f = w; f < NF; f += 8) {
        const float* src = (f < S_) ? (xs + f * TC) : (ms + (f - S_) * TC);
        float p = 0.f;
#pragma unroll
        for (int j = lane; j < TC; j += 32) p += valid[j] * src[j];
        p = wred(p);
        if (lane == 0) g_px[((size_t)chunk * B_ + b) * NF + f] = p;
    }
}

// ---------------------------------------------------------------------------
// Stage 2: per-batch tiny MLP. One CTA per batch row, 288 threads so all
// 264 merge outputs are produced in a single pass. K-loops are blocked by
// KB=24 with independent products to keep ~24 loads in flight per thread.
// ---------------------------------------------------------------------------
#define KB 24

__global__ __launch_bounds__(288) void stage2(
    const float* __restrict__ stat,
    const float* __restrict__ Ws,  const float* __restrict__ bs,
    const float* __restrict__ Wt,  const float* __restrict__ bt,
    const float* __restrict__ Wst, const float* __restrict__ bst,
    const float* __restrict__ Wm,  const float* __restrict__ bm,
    const float* __restrict__ Wc,  const float* __restrict__ bc,
    float* __restrict__ out) {
    __shared__ float xsum[NF];
    __shared__ float comb[MERGED_];
    __shared__ float comb2[MERGED_];
    __shared__ float sden[2];   // [0]=denom, [1]=tsum/denom

    const int b = blockIdx.x;
    const int tid = threadIdx.x;

    // Reduce per-chunk partials.
    if (tid < NF) {
        float a = 0.f;
#pragma unroll
        for (int c = 0; c < NCHUNK; c++) a += g_px[((size_t)c * B_ + b) * NF + tid];
        xsum[tid] = a;
    }
    if (tid == NF) {
        float a = 0.f, t = 0.f;
#pragma unroll
        for (int c = 0; c < NCHUNK; c++) { a += g_pm[c * B_ + b]; t += g_pt[c * B_ + b]; }
        float den = fmaxf(a, 1e-9f);
        sden[0] = den;
        sden[1] = t / den;
    }
    __syncthreads();

    const float den = sden[0], tsc = sden[1];

    // pooled[d] projection (K=74), deep-MLP blocked.
    if (tid < D_) {
        float p = 0.f;
        {
            float part[KB];
#pragma unroll
            for (int i0 = 0; i0 < 72; i0 += KB) {
#pragma unroll
                for (int k = 0; k < KB; k++)
                    part[k] = xsum[i0 + k] * Ws[(i0 + k) * D_ + tid];
#pragma unroll
                for (int k = 0; k < KB; k++) p += part[k];
            }
            p += xsum[72] * Ws[72 * D_ + tid];
            p += xsum[73] * Ws[73 * D_ + tid];
        }
        comb[tid] = p / den + bs[tid] + bt[tid] + tsc * Wt[tid];
    }
    // static embedding (8 dims) on the spare warp.
    if (tid >= 256 && tid < 256 + ST_) {
        const int j = tid - 256;
        float p = bst[j];
#pragma unroll
        for (int i = 0; i < ST_; i++) p += stat[b * ST_ + i] * Wst[i * ST_ + j];
        comb[D_ + j] = p;
    }
    __syncthreads();

    // merge: relu(comb @ Wm + bm). 264 outputs, one per thread, single pass.
    if (tid < MERGED_) {
        float p = bm[tid];
        float part[KB];
#pragma unroll
        for (int i0 = 0; i0 < MERGED_; i0 += KB) {   // 264 = 11 * 24
#pragma unroll
            for (int k = 0; k < KB; k++)
                part[k] = comb[i0 + k] * Wm[(i0 + k) * MERGED_ + tid];
#pragma unroll
            for (int k = 0; k < KB; k++) p += part[k];
        }
        comb2[tid] = fmaxf(p, 0.f);
    }
    __syncthreads();

    // classifier: warp 0 -> class 0, warp 1 -> class 1.
    const int w = tid >> 5, lane = tid & 31;
    if (w < C_) {
        float p = 0.f;
#pragma unroll
        for (int i = lane; i < MERGED_; i += 32) p += comb2[i] * Wc[i * C_ + w];
        p = wred(p);
        if (lane == 0) out[b * C_ + w] = p + bc[w];
    }
}

extern "C" void kernel_launch(void* const* d_in, const int* in_sizes, int n_in,
                              void* d_out, int out_size) {
    const float* x   = (const float*)d_in[0];
    const float* st  = (const float*)d_in[1];
    const float* tm  = (const float*)d_in[2];
    const int*   smk = (const int*)  d_in[3];
    const float* Ws  = (const float*)d_in[4];
    const float* bs  = (const float*)d_in[5];
    const float* Wt  = (const float*)d_in[6];
    const float* bt  = (const float*)d_in[7];
    const float* Wst = (const float*)d_in[8];
    const float* bst = (const float*)d_in[9];
    const float* Wm  = (const float*)d_in[10];
    const float* bm  = (const float*)d_in[11];
    const float* Wc  = (const float*)d_in[12];
    const float* bc  = (const float*)d_in[13];

    stage1<<<dim3(NCHUNK, B_), 256>>>(x, smk, tm);
    stage2<<<B_, 288>>>(st, Ws, bs, Wt, bt, Wst, bst, Wm, bm, Wc, bc,
                        (float*)d_out);
}